// round 3
// baseline (speedup 1.0000x reference)
#include <cuda_runtime.h>
#include <cuda_bf16.h>
#include <math.h>
#include <stdint.h>

// Problem constants (fixed shapes)
#define NTOK   4096
#define NHEAD  8
#define NSAMP  27
#define CDIM   512
#define QKVW   1536

// -------- scratch (device globals; no allocations allowed) --------
__device__ float g_qkv[NTOK * QKVW];        // fp32 qkv (N, 3C)
__device__ float g_off[NHEAD * NTOK * 81];  // offsets per (h,n)
__device__ float g_ao [NTOK * CDIM];        // attention output fp32
// bf16 hi/lo splits for tensor-core GEMMs
__device__ __nv_bfloat16 g_xhi[NTOK * CDIM], g_xlo[NTOK * CDIM];
__device__ __nv_bfloat16 g_wqh[QKVW * CDIM], g_wql[QKVW * CDIM];
__device__ __nv_bfloat16 g_wph[CDIM * CDIM], g_wpl[CDIM * CDIM];
__device__ __nv_bfloat16 g_aoh[NTOK * CDIM], g_aol[NTOK * CDIM];

// ============================================================
// mma.sync m16n8k16 bf16 (row.col), fp32 accum
// ============================================================
__device__ __forceinline__ void mma16816(
    float& d0, float& d1, float& d2, float& d3,
    uint32_t a0, uint32_t a1, uint32_t a2, uint32_t a3,
    uint32_t b0, uint32_t b1)
{
    asm volatile(
        "mma.sync.aligned.m16n8k16.row.col.f32.bf16.bf16.f32 "
        "{%0,%1,%2,%3}, {%4,%5,%6,%7}, {%8,%9}, {%0,%1,%2,%3};"
        : "+f"(d0), "+f"(d1), "+f"(d2), "+f"(d3)
        : "r"(a0), "r"(a1), "r"(a2), "r"(a3), "r"(b0), "r"(b1));
}

// ============================================================
// bf16x3 GEMM: C[M,N] = (Ahi+Alo)[M,K] @ (Bhi+Blo)[N,K]^T (+bias)
// CTA tile 128x128, BK=32, 256 threads; warp tile 32(m) x 64(n).
// Smem rows padded to 40 bf16 (80B) -> conflict-free frag LDS.
// ============================================================
#define SSTRIDE 40

__global__ void __launch_bounds__(256) gemm_mma(
    const __nv_bfloat16* __restrict__ Ahi, const __nv_bfloat16* __restrict__ Alo,
    const __nv_bfloat16* __restrict__ Bhi, const __nv_bfloat16* __restrict__ Blo,
    const float* __restrict__ bias, float* __restrict__ C, int N, int K)
{
    __shared__ __nv_bfloat16 sAh[128 * SSTRIDE];
    __shared__ __nv_bfloat16 sAl[128 * SSTRIDE];
    __shared__ __nv_bfloat16 sBh[128 * SSTRIDE];
    __shared__ __nv_bfloat16 sBl[128 * SSTRIDE];

    const int tid = threadIdx.x;
    const int wid = tid >> 5, lane = tid & 31;
    const int m0 = blockIdx.y * 128, n0 = blockIdx.x * 128;
    const int wm = (wid >> 1) * 32;      // warp m offset within CTA tile
    const int wn = (wid & 1) * 64;       // warp n offset

    const int lr = lane >> 2;            // 0..7
    const int lk = (lane & 3) * 2;       // 0,2,4,6

    float acc[2][8][4];
#pragma unroll
    for (int t = 0; t < 2; t++)
#pragma unroll
        for (int u = 0; u < 8; u++)
#pragma unroll
            for (int r = 0; r < 4; r++) acc[t][u][r] = 0.f;

    // G2S mapping: per tile, thread loads 2 uint4 (8 bf16 each)
    const int grow0 = tid >> 2, gc0 = tid & 3;           // idx = tid
    const int grow1 = (tid + 256) >> 2, gc1 = tid & 3;   // idx = tid+256

    for (int kb = 0; kb < K; kb += 32) {
        {
            const size_t ga0 = (size_t)(m0 + grow0) * K + kb + gc0 * 8;
            const size_t ga1 = (size_t)(m0 + grow1) * K + kb + gc1 * 8;
            const size_t gb0 = (size_t)(n0 + grow0) * K + kb + gc0 * 8;
            const size_t gb1 = (size_t)(n0 + grow1) * K + kb + gc1 * 8;
            const int sa0 = grow0 * SSTRIDE + gc0 * 8;
            const int sa1 = grow1 * SSTRIDE + gc1 * 8;
            *(uint4*)(sAh + sa0) = *(const uint4*)(Ahi + ga0);
            *(uint4*)(sAh + sa1) = *(const uint4*)(Ahi + ga1);
            *(uint4*)(sAl + sa0) = *(const uint4*)(Alo + ga0);
            *(uint4*)(sAl + sa1) = *(const uint4*)(Alo + ga1);
            *(uint4*)(sBh + sa0) = *(const uint4*)(Bhi + gb0);
            *(uint4*)(sBh + sa1) = *(const uint4*)(Bhi + gb1);
            *(uint4*)(sBl + sa0) = *(const uint4*)(Blo + gb0);
            *(uint4*)(sBl + sa1) = *(const uint4*)(Blo + gb1);
        }
        __syncthreads();

#pragma unroll
        for (int ks = 0; ks < 2; ks++) {
            const int ko = ks * 16 + lk;
            // B fragments: 8 n-tiles, hi & lo
            uint32_t bh[8][2], bl[8][2];
#pragma unroll
            for (int u = 0; u < 8; u++) {
                const int nrow = wn + u * 8 + lr;
                bh[u][0] = *(const uint32_t*)(sBh + nrow * SSTRIDE + ko);
                bh[u][1] = *(const uint32_t*)(sBh + nrow * SSTRIDE + ko + 8);
                bl[u][0] = *(const uint32_t*)(sBl + nrow * SSTRIDE + ko);
                bl[u][1] = *(const uint32_t*)(sBl + nrow * SSTRIDE + ko + 8);
            }
#pragma unroll
            for (int t = 0; t < 2; t++) {
                const int arow = wm + t * 16 + lr;
                uint32_t ah0 = *(const uint32_t*)(sAh + arow * SSTRIDE + ko);
                uint32_t ah1 = *(const uint32_t*)(sAh + (arow + 8) * SSTRIDE + ko);
                uint32_t ah2 = *(const uint32_t*)(sAh + arow * SSTRIDE + ko + 8);
                uint32_t ah3 = *(const uint32_t*)(sAh + (arow + 8) * SSTRIDE + ko + 8);
                uint32_t al0 = *(const uint32_t*)(sAl + arow * SSTRIDE + ko);
                uint32_t al1 = *(const uint32_t*)(sAl + (arow + 8) * SSTRIDE + ko);
                uint32_t al2 = *(const uint32_t*)(sAl + arow * SSTRIDE + ko + 8);
                uint32_t al3 = *(const uint32_t*)(sAl + (arow + 8) * SSTRIDE + ko + 8);
#pragma unroll
                for (int u = 0; u < 8; u++) {
                    mma16816(acc[t][u][0], acc[t][u][1], acc[t][u][2], acc[t][u][3],
                             ah0, ah1, ah2, ah3, bh[u][0], bh[u][1]);
                    mma16816(acc[t][u][0], acc[t][u][1], acc[t][u][2], acc[t][u][3],
                             ah0, ah1, ah2, ah3, bl[u][0], bl[u][1]);
                    mma16816(acc[t][u][0], acc[t][u][1], acc[t][u][2], acc[t][u][3],
                             al0, al1, al2, al3, bh[u][0], bh[u][1]);
                }
            }
        }
        __syncthreads();
    }

    // Epilogue: accum layout m16n8: d0,d1 = row lr, cols lk..lk+1 ; d2,d3 = row lr+8
#pragma unroll
    for (int t = 0; t < 2; t++) {
#pragma unroll
        for (int u = 0; u < 8; u++) {
            const int col = n0 + wn + u * 8 + lk;
            float b0 = 0.f, b1 = 0.f;
            if (bias) { b0 = __ldg(bias + col); b1 = __ldg(bias + col + 1); }
            const int row0 = m0 + wm + t * 16 + lr;
            float2 v0, v1;
            v0.x = acc[t][u][0] + b0; v0.y = acc[t][u][1] + b1;
            v1.x = acc[t][u][2] + b0; v1.y = acc[t][u][3] + b1;
            *(float2*)(C + (size_t)row0 * N + col) = v0;
            *(float2*)(C + (size_t)(row0 + 8) * N + col) = v1;
        }
    }
}

// ============================================================
// fp32 -> bf16 hi/lo split (4 floats per thread)
// ============================================================
__global__ void __launch_bounds__(256) split_kernel(
    const float4* __restrict__ src, uint2* __restrict__ hi, uint2* __restrict__ lo, int n4)
{
    const int i = blockIdx.x * 256 + threadIdx.x;
    if (i >= n4) return;
    const float4 v = src[i];
    union { __nv_bfloat16 b[4]; uint2 u; } H, L;
    H.b[0] = __float2bfloat16(v.x); H.b[1] = __float2bfloat16(v.y);
    H.b[2] = __float2bfloat16(v.z); H.b[3] = __float2bfloat16(v.w);
    L.b[0] = __float2bfloat16(v.x - __bfloat162float(H.b[0]));
    L.b[1] = __float2bfloat16(v.y - __bfloat162float(H.b[1]));
    L.b[2] = __float2bfloat16(v.z - __bfloat162float(H.b[2]));
    L.b[3] = __float2bfloat16(v.w - __bfloat162float(H.b[3]));
    hi[i] = H.u; lo[i] = L.u;
}

// ============================================================
// Offsets: g_off[(h*N+n)*81 + c] = sum_d x[n, h*64+d] * w_off[c, d]
// ============================================================
__global__ void __launch_bounds__(256) offset_kernel(
    const float* __restrict__ x, const float* __restrict__ w_off)
{
    __shared__ float xs[CDIM];
    __shared__ float wT[64 * 81];
    const int n = blockIdx.x, tid = threadIdx.x;
    for (int i = tid; i < CDIM; i += 256) xs[i] = x[(size_t)n * CDIM + i];
    for (int i = tid; i < 81 * 64; i += 256) {
        int c = i >> 6, k = i & 63;
        wT[k * 81 + c] = w_off[i];
    }
    __syncthreads();
    for (int idx = tid; idx < NHEAD * 81; idx += 256) {
        const int h = idx / 81, c = idx - h * 81;
        const float* xh = xs + h * 64;
        float acc = 0.f;
#pragma unroll 8
        for (int k = 0; k < 64; k++) acc = fmaf(xh[k], wT[k * 81 + c], acc);
        g_off[((size_t)h * NTOK + n) * 81 + c] = acc;
    }
}

// ============================================================
// Fused deformable attention: warp per (head, token); lane owns 2 channels.
// Branch-free 8-corner trilinear (clamped index + zeroed weight).
// ============================================================
__device__ __forceinline__ void corner_setup(
    int z, int y, int x, int s, float soz, float soy, float sox,
    int idx[8], float w[8])
{
    const float pz = (float)(z + s / 9 - 1) + soz;
    const float py = (float)(y + (s / 3) % 3 - 1) + soy;
    const float px = (float)(x + s % 3 - 1) + sox;
    const float fz = floorf(pz), fy = floorf(py), fx = floorf(px);
    const float wz = pz - fz, wy = py - fy, wx = px - fx;
    const int iz = (int)fz, iy = (int)fy, ix = (int)fx;
    const int z0 = min(max(iz, 0), 15), z1 = min(max(iz + 1, 0), 15);
    const int y0 = min(max(iy, 0), 15), y1 = min(max(iy + 1, 0), 15);
    const int x0 = min(max(ix, 0), 15), x1 = min(max(ix + 1, 0), 15);
    const float wz0 = ((unsigned)iz < 16u) ? 1.f - wz : 0.f;
    const float wz1 = ((unsigned)(iz + 1) < 16u) ? wz : 0.f;
    const float wy0 = ((unsigned)iy < 16u) ? 1.f - wy : 0.f;
    const float wy1 = ((unsigned)(iy + 1) < 16u) ? wy : 0.f;
    const float wx0 = ((unsigned)ix < 16u) ? 1.f - wx : 0.f;
    const float wx1 = ((unsigned)(ix + 1) < 16u) ? wx : 0.f;
    idx[0] = (z0 * 16 + y0) * 16 + x0;  w[0] = wz0 * wy0 * wx0;
    idx[1] = (z0 * 16 + y0) * 16 + x1;  w[1] = wz0 * wy0 * wx1;
    idx[2] = (z0 * 16 + y1) * 16 + x0;  w[2] = wz0 * wy1 * wx0;
    idx[3] = (z0 * 16 + y1) * 16 + x1;  w[3] = wz0 * wy1 * wx1;
    idx[4] = (z1 * 16 + y0) * 16 + x0;  w[4] = wz1 * wy0 * wx0;
    idx[5] = (z1 * 16 + y0) * 16 + x1;  w[5] = wz1 * wy0 * wx1;
    idx[6] = (z1 * 16 + y1) * 16 + x0;  w[6] = wz1 * wy1 * wx0;
    idx[7] = (z1 * 16 + y1) * 16 + x1;  w[7] = wz1 * wy1 * wx1;
}

__global__ void __launch_bounds__(128) attn_kernel(
    const float* __restrict__ rel_d, const float* __restrict__ rel_h,
    const float* __restrict__ rel_w)
{
    const int warp = threadIdx.x >> 5;
    const int lane = threadIdx.x & 31;
    const int n = blockIdx.x * 4 + warp;
    const int h = blockIdx.y;
    const int z = n >> 8, y = (n >> 4) & 15, x = n & 15;
    const int c0 = lane << 1;

    const float* qkv = g_qkv;
    const float2 qa = *(const float2*)(qkv + (size_t)n * QKVW + h * 64 + c0);
    const int nzx = (z * 16 + x) * 16 + y;
    const int nxz = (x * 16 + z) * 16 + y;
    const float2 qb = *(const float2*)(qkv + (size_t)nzx * QKVW + h * 64 + c0);
    const float2 qc = *(const float2*)(qkv + (size_t)nxz * QKVW + h * 64 + c0);

    const float* offp = g_off + ((size_t)h * NTOK + n) * 81;
    float oz = 0.f, oy = 0.f, ox = 0.f;
    if (lane < NSAMP) {
        oz = offp[lane * 3 + 0];
        oy = offp[lane * 3 + 1];
        ox = offp[lane * 3 + 2];
    }

    const float* kb = qkv + 512  + h * 64 + c0;
    const float* vb = qkv + 1024 + h * 64 + c0;

    float lg[NSAMP];
#pragma unroll
    for (int s = 0; s < NSAMP; s++) {
        const float soz = __shfl_sync(0xffffffffu, oz, s);
        const float soy = __shfl_sync(0xffffffffu, oy, s);
        const float sox = __shfl_sync(0xffffffffu, ox, s);
        int idx[8]; float w[8];
        corner_setup(z, y, x, s, soz, soy, sox, idx, w);
        float2 kc_[8];
#pragma unroll
        for (int c = 0; c < 8; c++)
            kc_[c] = *(const float2*)(kb + (size_t)idx[c] * QKVW);
        float part = 0.f;
#pragma unroll
        for (int c = 0; c < 8; c++)
            part = fmaf(w[c], fmaf(kc_[c].x, qa.x, kc_[c].y * qa.y), part);

        const int j = 15 + s - x;
        const float2 rwv = *(const float2*)(rel_w + j * 64 + c0);
        const float2 rhv = *(const float2*)(rel_h + j * 64 + c0);
        const float2 rdv = *(const float2*)(rel_d + j * 64 + c0);
        float val = 0.125f * part
                  + qa.x * rwv.x + qa.y * rwv.y
                  + qb.x * rhv.x + qb.y * rhv.y
                  + qc.x * rdv.x + qc.y * rdv.y;
#pragma unroll
        for (int o = 16; o > 0; o >>= 1)
            val += __shfl_xor_sync(0xffffffffu, val, o);
        lg[s] = val;
    }

    float mx = lg[0];
#pragma unroll
    for (int s = 1; s < NSAMP; s++) mx = fmaxf(mx, lg[s]);
    float ssum = 0.f;
#pragma unroll
    for (int s = 0; s < NSAMP; s++) { lg[s] = expf(lg[s] - mx); ssum += lg[s]; }
    const float inv = 1.f / ssum;

    float a0 = 0.f, a1 = 0.f;
#pragma unroll
    for (int s = 0; s < NSAMP; s++) {
        const float soz = __shfl_sync(0xffffffffu, oz, s);
        const float soy = __shfl_sync(0xffffffffu, oy, s);
        const float sox = __shfl_sync(0xffffffffu, ox, s);
        int idx[8]; float w[8];
        corner_setup(z, y, x, s, soz, soy, sox, idx, w);
        float2 vc[8];
#pragma unroll
        for (int c = 0; c < 8; c++)
            vc[c] = *(const float2*)(vb + (size_t)idx[c] * QKVW);
        const float p = lg[s];
#pragma unroll
        for (int c = 0; c < 8; c++) {
            const float pw = p * w[c];
            a0 = fmaf(pw, vc[c].x, a0);
            a1 = fmaf(pw, vc[c].y, a1);
        }
    }

    float2 res; res.x = a0 * inv; res.y = a1 * inv;
    *(float2*)(g_ao + (size_t)n * CDIM + h * 64 + c0) = res;
}

// ============================================================
extern "C" void kernel_launch(void* const* d_in, const int* in_sizes, int n_in,
                              void* d_out, int out_size)
{
    const float* x      = (const float*)d_in[0];
    const float* w_qkv  = (const float*)d_in[1];
    const float* w_proj = (const float*)d_in[2];
    const float* b_proj = (const float*)d_in[3];
    const float* w_off  = (const float*)d_in[4];
    const float* rel_d  = (const float*)d_in[5];
    const float* rel_h  = (const float*)d_in[6];
    const float* rel_w  = (const float*)d_in[7];
    float* out = (float*)d_out;

    float *qkv_p, *ao_p;
    __nv_bfloat16 *xhi, *xlo, *wqh, *wql, *wph, *wpl, *aoh, *aol;
    cudaGetSymbolAddress((void**)&qkv_p, g_qkv);
    cudaGetSymbolAddress((void**)&ao_p,  g_ao);
    cudaGetSymbolAddress((void**)&xhi, g_xhi); cudaGetSymbolAddress((void**)&xlo, g_xlo);
    cudaGetSymbolAddress((void**)&wqh, g_wqh); cudaGetSymbolAddress((void**)&wql, g_wql);
    cudaGetSymbolAddress((void**)&wph, g_wph); cudaGetSymbolAddress((void**)&wpl, g_wpl);
    cudaGetSymbolAddress((void**)&aoh, g_aoh); cudaGetSymbolAddress((void**)&aol, g_aol);

    // fp32 -> bf16 hi/lo splits
    {
        int n4;
        n4 = NTOK * CDIM / 4;
        split_kernel<<<(n4 + 255) / 256, 256>>>((const float4*)x, (uint2*)xhi, (uint2*)xlo, n4);
        n4 = QKVW * CDIM / 4;
        split_kernel<<<(n4 + 255) / 256, 256>>>((const float4*)w_qkv, (uint2*)wqh, (uint2*)wql, n4);
        n4 = CDIM * CDIM / 4;
        split_kernel<<<(n4 + 255) / 256, 256>>>((const float4*)w_proj, (uint2*)wph, (uint2*)wpl, n4);
    }

    // per-head deformable offsets (fp32 SIMT)
    offset_kernel<<<NTOK, 256>>>(x, w_off);

    // qkv = x @ w_qkv^T   (M=4096, N=1536, K=512) -> fp32 g_qkv
    gemm_mma<<<dim3(QKVW / 128, NTOK / 128), 256>>>(
        xhi, xlo, wqh, wql, nullptr, qkv_p, QKVW, CDIM);

    // fused deformable attention
    attn_kernel<<<dim3(NTOK / 4, NHEAD), 128>>>(rel_d, rel_h, rel_w);

    // split attention output, then proj GEMM
    {
        int n4 = NTOK * CDIM / 4;
        split_kernel<<<(n4 + 255) / 256, 256>>>((const float4*)ao_p, (uint2*)aoh, (uint2*)aol, n4);
    }
    gemm_mma<<<dim3(CDIM / 128, NTOK / 128), 256>>>(
        aoh, aol, wph, wpl, b_proj, out, CDIM, CDIM);
}

// round 4
// speedup vs baseline: 3.0220x; 3.0220x over previous
#include <cuda_runtime.h>
#include <math.h>
#include <stdint.h>

typedef unsigned long long ull;

// Problem constants (fixed shapes)
#define NTOK   4096
#define NHEAD  8
#define NSAMP  27
#define CDIM   512
#define QKVW   1536

// -------- scratch (device globals; no allocations allowed) --------
__device__ float g_qkv[NTOK * QKVW];        // fp32 qkv (N, 3C)
__device__ float g_off[NHEAD * NTOK * 81];  // offsets per (h,n)
__device__ float g_ao [NTOK * CDIM];        // attention output fp32

// ============================================================
// Packed fp32x2 FMA (Blackwell): d = a*b + d (two independent fp32 lanes)
// ============================================================
#define FMA2(d, a, b) \
    asm("fma.rn.f32x2 %0, %1, %2, %0;" : "+l"(d) : "l"(a), "l"(b))

// ============================================================
// f32x2 SGEMM (NT): C[M,N] = A[M,K] @ W[N,K]^T (+ bias)
// BM=BN=128, BK=8, 256 threads, 8x8 microtile as 8x4 f32x2 pairs.
// A smem: duplicated pairs [m][{a,a} x8k], row stride 18 floats.
// W smem: k-major [k][n], row stride 132 floats (conflict-free STS).
// Double-buffered, register-staged G2S.
// ============================================================
__global__ void __launch_bounds__(256, 2) sgemm_f32x2(
    const float* __restrict__ A, const float* __restrict__ W,
    const float* __restrict__ bias, float* __restrict__ C, int N, int K)
{
    __shared__ __align__(16) float As[2][128][18];
    __shared__ __align__(16) float Ws[2][8][132];

    const int tid = threadIdx.x;
    const int tx = tid & 15;          // n-dir (8 cols each)
    const int ty = tid >> 4;          // m-dir (8 rows each)
    const int m0 = blockIdx.y * 128, n0 = blockIdx.x * 128;
    const int lr = tid >> 1;          // 0..127 load row
    const int lk = (tid & 1) * 4;     // k sub-chunk

    const float* Ap = A + (size_t)(m0 + lr) * K + lk;
    const float* Wp = W + (size_t)(n0 + lr) * K + lk;

    ull acc[8][4];
#pragma unroll
    for (int i = 0; i < 8; i++)
#pragma unroll
        for (int j = 0; j < 4; j++) acc[i][j] = 0ULL;

    // prologue: stage 0
    float4 va = *(const float4*)Ap;
    float4 wv = *(const float4*)Wp;
    {
        float av[4] = {va.x, va.y, va.z, va.w};
        float wvv[4] = {wv.x, wv.y, wv.z, wv.w};
#pragma unroll
        for (int i = 0; i < 4; i++) {
            *(float2*)&As[0][lr][2 * (lk + i)] = make_float2(av[i], av[i]);
            Ws[0][lk + i][lr] = wvv[i];
        }
    }
    __syncthreads();

    const int nst = K >> 3;
    for (int st = 0; st < nst; st++) {
        const int buf = st & 1;
        float4 va2, wv2;
        const bool has = (st + 1) < nst;
        if (has) {
            va2 = *(const float4*)(Ap + (st + 1) * 8);
            wv2 = *(const float4*)(Wp + (st + 1) * 8);
        }
#pragma unroll
        for (int kk = 0; kk < 8; kk++) {
            ull a2[8];
#pragma unroll
            for (int i = 0; i < 8; i++)
                a2[i] = *(const ull*)&As[buf][ty * 8 + i][2 * kk];
            ulonglong2 q0 = *(const ulonglong2*)&Ws[buf][kk][tx * 8];
            ulonglong2 q1 = *(const ulonglong2*)&Ws[buf][kk][tx * 8 + 4];
            ull b2[4] = {q0.x, q0.y, q1.x, q1.y};
#pragma unroll
            for (int i = 0; i < 8; i++) {
                FMA2(acc[i][0], a2[i], b2[0]);
                FMA2(acc[i][1], a2[i], b2[1]);
                FMA2(acc[i][2], a2[i], b2[2]);
                FMA2(acc[i][3], a2[i], b2[3]);
            }
        }
        __syncthreads();
        if (has) {
            float av[4] = {va2.x, va2.y, va2.z, va2.w};
            float wvv[4] = {wv2.x, wv2.y, wv2.z, wv2.w};
            const int nb = buf ^ 1;
#pragma unroll
            for (int i = 0; i < 4; i++) {
                *(float2*)&As[nb][lr][2 * (lk + i)] = make_float2(av[i], av[i]);
                Ws[nb][lk + i][lr] = wvv[i];
            }
        }
        __syncthreads();
    }

    // epilogue
    float bv[8];
#pragma unroll
    for (int j = 0; j < 8; j++)
        bv[j] = bias ? __ldg(bias + n0 + tx * 8 + j) : 0.f;

#pragma unroll
    for (int i = 0; i < 8; i++) {
        union { ull u; float2 f; } p[4];
#pragma unroll
        for (int j = 0; j < 4; j++) p[j].u = acc[i][j];
        float4 o0, o1;
        o0.x = p[0].f.x + bv[0]; o0.y = p[0].f.y + bv[1];
        o0.z = p[1].f.x + bv[2]; o0.w = p[1].f.y + bv[3];
        o1.x = p[2].f.x + bv[4]; o1.y = p[2].f.y + bv[5];
        o1.z = p[3].f.x + bv[6]; o1.w = p[3].f.y + bv[7];
        float* cp = C + (size_t)(m0 + ty * 8 + i) * N + n0 + tx * 8;
        *(float4*)cp = o0;
        *(float4*)(cp + 4) = o1;
    }
}

// ============================================================
// Offsets: g_off[(h*N+n)*81 + c] = sum_k x[n, h*64+k] * w_off[c, k]
// thread per (h, n); x row in registers, w_off broadcast from smem.
// ============================================================
__global__ void __launch_bounds__(256) offset_kernel(
    const float* __restrict__ x, const float* __restrict__ w_off)
{
    __shared__ float sw[81 * 64];
    const int tid = threadIdx.x;
    for (int i = tid; i < 81 * 64 / 4; i += 256)
        ((float4*)sw)[i] = ((const float4*)w_off)[i];
    __syncthreads();

    const int g = blockIdx.x * 256 + tid;
    const int h = g & 7, n = g >> 3;

    float4 xr[16];
    const float4* xp = (const float4*)(x + (size_t)n * CDIM + h * 64);
#pragma unroll
    for (int i = 0; i < 16; i++) xr[i] = xp[i];

    float* op = g_off + ((size_t)h * NTOK + n) * 81;
    for (int c = 0; c < 81; c++) {
        const float4* wp = (const float4*)(sw + c * 64);
        float acc = 0.f;
#pragma unroll
        for (int i = 0; i < 16; i++) {
            float4 w4 = wp[i];
            acc = fmaf(w4.x, xr[i].x, acc);
            acc = fmaf(w4.y, xr[i].y, acc);
            acc = fmaf(w4.z, xr[i].z, acc);
            acc = fmaf(w4.w, xr[i].w, acc);
        }
        op[c] = acc;
    }
}

// ============================================================
// Fused deformable attention, single pass (online softmax).
// warp per (head, token); lane owns 2 channels; rel tables in smem.
// ============================================================
__device__ __forceinline__ void corner_setup(
    int z, int y, int x, int s, float soz, float soy, float sox,
    int idx[8], float w[8])
{
    const float pz = (float)(z + s / 9 - 1) + soz;
    const float py = (float)(y + (s / 3) % 3 - 1) + soy;
    const float px = (float)(x + s % 3 - 1) + sox;
    const float fz = floorf(pz), fy = floorf(py), fx = floorf(px);
    const float wz = pz - fz, wy = py - fy, wx = px - fx;
    const int iz = (int)fz, iy = (int)fy, ix = (int)fx;
    const int z0 = min(max(iz, 0), 15), z1 = min(max(iz + 1, 0), 15);
    const int y0 = min(max(iy, 0), 15), y1 = min(max(iy + 1, 0), 15);
    const int x0 = min(max(ix, 0), 15), x1 = min(max(ix + 1, 0), 15);
    const float wz0 = ((unsigned)iz < 16u) ? 1.f - wz : 0.f;
    const float wz1 = ((unsigned)(iz + 1) < 16u) ? wz : 0.f;
    const float wy0 = ((unsigned)iy < 16u) ? 1.f - wy : 0.f;
    const float wy1 = ((unsigned)(iy + 1) < 16u) ? wy : 0.f;
    const float wx0 = ((unsigned)ix < 16u) ? 1.f - wx : 0.f;
    const float wx1 = ((unsigned)(ix + 1) < 16u) ? wx : 0.f;
    idx[0] = (z0 * 16 + y0) * 16 + x0;  w[0] = wz0 * wy0 * wx0;
    idx[1] = (z0 * 16 + y0) * 16 + x1;  w[1] = wz0 * wy0 * wx1;
    idx[2] = (z0 * 16 + y1) * 16 + x0;  w[2] = wz0 * wy1 * wx0;
    idx[3] = (z0 * 16 + y1) * 16 + x1;  w[3] = wz0 * wy1 * wx1;
    idx[4] = (z1 * 16 + y0) * 16 + x0;  w[4] = wz1 * wy0 * wx0;
    idx[5] = (z1 * 16 + y0) * 16 + x1;  w[5] = wz1 * wy0 * wx1;
    idx[6] = (z1 * 16 + y1) * 16 + x0;  w[6] = wz1 * wy1 * wx0;
    idx[7] = (z1 * 16 + y1) * 16 + x1;  w[7] = wz1 * wy1 * wx1;
}

__global__ void __launch_bounds__(256) attn_kernel(
    const float* __restrict__ rel_d, const float* __restrict__ rel_h,
    const float* __restrict__ rel_w)
{
    __shared__ float srel[3 * 42 * 64];   // [w | h | d]
    const int tid = threadIdx.x;
    {
        float4* s4 = (float4*)srel;
        const float4* rw4 = (const float4*)rel_w;
        const float4* rh4 = (const float4*)rel_h;
        const float4* rd4 = (const float4*)rel_d;
        for (int i = tid; i < 672; i += 256) {
            s4[i] = rw4[i];
            s4[672 + i] = rh4[i];
            s4[1344 + i] = rd4[i];
        }
    }
    __syncthreads();

    const int warp = tid >> 5;
    const int lane = tid & 31;
    const int n = blockIdx.x * 8 + warp;
    const int h = blockIdx.y;
    const int z = n >> 8, y = (n >> 4) & 15, x = n & 15;
    const int c0 = lane << 1;

    const float* qkv = g_qkv;
    const float2 qa = *(const float2*)(qkv + (size_t)n * QKVW + h * 64 + c0);
    const int nzx = (z * 16 + x) * 16 + y;
    const int nxz = (x * 16 + z) * 16 + y;
    const float2 qb = *(const float2*)(qkv + (size_t)nzx * QKVW + h * 64 + c0);
    const float2 qc = *(const float2*)(qkv + (size_t)nxz * QKVW + h * 64 + c0);

    const float* offp = g_off + ((size_t)h * NTOK + n) * 81;
    float oz = 0.f, oy = 0.f, ox = 0.f;
    if (lane < NSAMP) {
        oz = offp[lane * 3 + 0];
        oy = offp[lane * 3 + 1];
        ox = offp[lane * 3 + 2];
    }

    const float* kb = qkv + 512  + h * 64 + c0;
    const float* vb = qkv + 1024 + h * 64 + c0;
    const float* swp = srel + c0;
    const float* shp = srel + 42 * 64 + c0;
    const float* sdp = srel + 84 * 64 + c0;

    float lgmax = -3.0e38f, ssum = 0.f, a0 = 0.f, a1 = 0.f;

#pragma unroll 3
    for (int s = 0; s < NSAMP; s++) {
        const float soz = __shfl_sync(0xffffffffu, oz, s);
        const float soy = __shfl_sync(0xffffffffu, oy, s);
        const float sox = __shfl_sync(0xffffffffu, ox, s);
        int idx[8]; float w[8];
        corner_setup(z, y, x, s, soz, soy, sox, idx, w);

        // k gather + dot
        float2 kc[8];
#pragma unroll
        for (int c = 0; c < 8; c++)
            kc[c] = *(const float2*)(kb + (size_t)idx[c] * QKVW);
        float part = 0.f;
#pragma unroll
        for (int c = 0; c < 8; c++)
            part = fmaf(w[c], fmaf(kc[c].x, qa.x, kc[c].y * qa.y), part);

        // positional embedding (smem)
        const int j = 15 + s - x;
        const float2 rwv = *(const float2*)(swp + j * 64);
        const float2 rhv = *(const float2*)(shp + j * 64);
        const float2 rdv = *(const float2*)(sdp + j * 64);
        float val = 0.125f * part
                  + qa.x * rwv.x + qa.y * rwv.y
                  + qb.x * rhv.x + qb.y * rhv.y
                  + qc.x * rdv.x + qc.y * rdv.y;
#pragma unroll
        for (int o = 16; o > 0; o >>= 1)
            val += __shfl_xor_sync(0xffffffffu, val, o);

        // online softmax update
        const float mnew = fmaxf(lgmax, val);
        const float corr = expf(lgmax - mnew);
        const float p = expf(val - mnew);
        ssum = ssum * corr + p;
        a0 *= corr; a1 *= corr;
        lgmax = mnew;

        // v gather + weighted accumulate
        float2 vc[8];
#pragma unroll
        for (int c = 0; c < 8; c++)
            vc[c] = *(const float2*)(vb + (size_t)idx[c] * QKVW);
#pragma unroll
        for (int c = 0; c < 8; c++) {
            const float pw = p * w[c];
            a0 = fmaf(pw, vc[c].x, a0);
            a1 = fmaf(pw, vc[c].y, a1);
        }
    }

    const float inv = 1.f / ssum;
    float2 res; res.x = a0 * inv; res.y = a1 * inv;
    *(float2*)(g_ao + (size_t)n * CDIM + h * 64 + c0) = res;
}

// ============================================================
extern "C" void kernel_launch(void* const* d_in, const int* in_sizes, int n_in,
                              void* d_out, int out_size)
{
    const float* x      = (const float*)d_in[0];
    const float* w_qkv  = (const float*)d_in[1];
    const float* w_proj = (const float*)d_in[2];
    const float* b_proj = (const float*)d_in[3];
    const float* w_off  = (const float*)d_in[4];
    const float* rel_d  = (const float*)d_in[5];
    const float* rel_h  = (const float*)d_in[6];
    const float* rel_w  = (const float*)d_in[7];
    float* out = (float*)d_out;

    float *qkv_p, *ao_p;
    cudaGetSymbolAddress((void**)&qkv_p, g_qkv);
    cudaGetSymbolAddress((void**)&ao_p,  g_ao);

    // per-head deformable offsets
    offset_kernel<<<NTOK * NHEAD / 256, 256>>>(x, w_off);

    // qkv = x @ w_qkv^T   (M=4096, N=1536, K=512)
    sgemm_f32x2<<<dim3(QKVW / 128, NTOK / 128), 256>>>(
        x, w_qkv, nullptr, qkv_p, QKVW, CDIM);

    // fused deformable attention (+ pos emb + online softmax)
    attn_kernel<<<dim3(NTOK / 8, NHEAD), 256>>>(rel_d, rel_h, rel_w);

    // out = attn_out @ w_proj^T + b_proj   (M=4096, N=512, K=512)
    sgemm_f32x2<<<dim3(CDIM / 128, NTOK / 128), 256>>>(
        ao_p, w_proj, b_proj, out, CDIM, CDIM);
}